// round 14
// baseline (speedup 1.0000x reference)
#include <cuda_runtime.h>
#include <cuda_fp16.h>

#define DD 64
#define NMAX 100000
#define EMAX 1250000
#define BMAX 4096
#define PAD 64

typedef unsigned long long u64;

__device__ __half g_h0[(size_t)NMAX * DD];            // fp16(emb[x]), graph-invariant
__device__ __half g_hb0[3][(size_t)NMAX * DD];        // layer-1 outputs (pre-scaled)
__device__ __half g_hb1[3][(size_t)NMAX * DD];        // layer-2 outputs (pre-scaled)
__device__ float  g_dinv[3 * NMAX];
// scratch: [0,M) deg/cursor, [M,2M) layer2 frontier flags, [2M,2M+8) worklist counts.
__device__ int    g_scratch[6 * NMAX + 8];
__device__ int    g_wl[3][NMAX];                      // compacted layer-2 worklists
__device__ int    g_csr[(size_t)3 * NMAX * PAD];      // padded CSR
__device__ unsigned int g_pairbm[(NMAX + 31) / 32];   // pair-node bitmap
__device__ float  g_wa[DD];

// ---- packed f32x2 helpers (ptxas never auto-fuses these) ----
__device__ __forceinline__ u64 h2f2(unsigned int h) {
    float2 f = __half22float2(*reinterpret_cast<const __half2*>(&h));
    u64 r; asm("mov.b64 %0, {%1, %2};" : "=l"(r) : "f"(f.x), "f"(f.y)); return r;
}
__device__ __forceinline__ u64 packf2(float x, float y) {
    u64 r; asm("mov.b64 %0, {%1, %2};" : "=l"(r) : "f"(x), "f"(y)); return r;
}
__device__ __forceinline__ float2 unpackf2(u64 a) {
    float x, y; asm("mov.b64 {%0, %1}, %2;" : "=f"(x), "=f"(y) : "l"(a));
    return make_float2(x, y);
}
__device__ __forceinline__ u64 fma2v(u64 a, u64 b, u64 c) {
    u64 d; asm("fma.rn.f32x2 %0, %1, %2, %3;" : "=l"(d) : "l"(a), "l"(b), "l"(c)); return d;
}
__device__ __forceinline__ u64 add2v(u64 a, u64 b) {
    u64 d; asm("add.rn.f32x2 %0, %1, %2;" : "=l"(d) : "l"(a), "l"(b)); return d;
}
__device__ __forceinline__ u64 mul2v(u64 a, u64 b) {
    u64 d; asm("mul.rn.f32x2 %0, %1, %2;" : "=l"(d) : "l"(a), "l"(b)); return d;
}

// Build pair-node bitmap (12.5 KB, L1-resident in fill_csr).
__global__ void pairbm_kernel(const int* __restrict__ user, const int* __restrict__ item, int B) {
    int j = blockIdx.x * blockDim.x + threadIdx.x;
    if (j >= 2 * B) return;
    int n = (j < B) ? user[j] : item[j - B];
    atomicOr(&g_pairbm[n >> 5], 1u << (n & 31));
}

// One pass: count + place + frontier-flag. gridDim.y = graph.
__global__ void fill_csr_kernel(const int* __restrict__ e0, const int* __restrict__ e1,
                                const int* __restrict__ e2, int E, int N, int M) {
    int g = blockIdx.y;
    const int* srcp = (g == 0 ? e0 : (g == 1 ? e1 : e2));
    const int* dstp = srcp + E;
    int* deg  = g_scratch + g * N;
    int* flag = g_scratch + M + g * N;
    int* csr  = g_csr + (size_t)g * N * PAD;
    int t = blockIdx.x * blockDim.x + threadIdx.x;
    int base = t * 4;
    if (base + 4 <= E) {
        int4 s = *reinterpret_cast<const int4*>(srcp + base);
        int4 d = *reinterpret_cast<const int4*>(dstp + base);
        int p;
        p = atomicAdd(&deg[d.x], 1); if (p < PAD) csr[(size_t)d.x * PAD + p] = s.x;
        p = atomicAdd(&deg[d.y], 1); if (p < PAD) csr[(size_t)d.y * PAD + p] = s.y;
        p = atomicAdd(&deg[d.z], 1); if (p < PAD) csr[(size_t)d.z * PAD + p] = s.z;
        p = atomicAdd(&deg[d.w], 1); if (p < PAD) csr[(size_t)d.w * PAD + p] = s.w;
        if ((g_pairbm[d.x >> 5] >> (d.x & 31)) & 1) flag[s.x] = 1;
        if ((g_pairbm[d.y >> 5] >> (d.y & 31)) & 1) flag[s.y] = 1;
        if ((g_pairbm[d.z >> 5] >> (d.z & 31)) & 1) flag[s.z] = 1;
        if ((g_pairbm[d.w >> 5] >> (d.w & 31)) & 1) flag[s.w] = 1;
    } else {
        for (int e = base; e < E; e++) {
            int d = dstp[e], s = srcp[e];
            int p = atomicAdd(&deg[d], 1);
            if (p < PAD) csr[(size_t)d * PAD + p] = s;
            if ((g_pairbm[d >> 5] >> (d & 31)) & 1) flag[s] = 1;
        }
    }
}

// Vectorized dinv: 4 nodes per thread.
__global__ void dinv_kernel(int M) {
    int i4 = (blockIdx.x * blockDim.x + threadIdx.x) * 4;
    if (i4 + 4 <= M) {
        int4 d = *reinterpret_cast<const int4*>(g_scratch + i4);
        float4 r;
        r.x = (d.x > 0) ? rsqrtf((float)d.x) : 0.0f;
        r.y = (d.y > 0) ? rsqrtf((float)d.y) : 0.0f;
        r.z = (d.z > 0) ? rsqrtf((float)d.z) : 0.0f;
        r.w = (d.w > 0) ? rsqrtf((float)d.w) : 0.0f;
        *reinterpret_cast<float4*>(g_dinv + i4) = r;
    } else {
        for (int i = i4; i < M; i++) {
            int d = g_scratch[i];
            g_dinv[i] = (d > 0) ? rsqrtf((float)d) : 0.0f;
        }
    }
}

// h0 = fp16(emb_table[x]); 8 lanes per row.
__global__ void build_h0_kernel(const float* __restrict__ emb, const int* __restrict__ x, int N) {
    int t = blockIdx.x * blockDim.x + threadIdx.x;
    int n = t >> 3, lane = t & 7;
    if (n >= N) return;
    int xr = x[n];
    const float4* row = reinterpret_cast<const float4*>(emb + (size_t)xr * DD);
    float4 a = row[lane * 2], b = row[lane * 2 + 1];
    __half2 o[4];
    o[0] = __floats2half2_rn(a.x, a.y);
    o[1] = __floats2half2_rn(a.z, a.w);
    o[2] = __floats2half2_rn(b.x, b.y);
    o[3] = __floats2half2_rn(b.z, b.w);
    reinterpret_cast<uint4*>(&g_h0[(size_t)n * DD])[lane] = *reinterpret_cast<uint4*>(o);
}

// Warp-aggregated compaction of flagged nodes into g_wl[g].
__global__ void compact_kernel(int N, int M) {
    int g = blockIdx.y;
    int n = blockIdx.x * blockDim.x + threadIdx.x;
    int lane = threadIdx.x & 31;
    bool act = (n < N) && (g_scratch[M + g * N + n] != 0);
    unsigned m = __ballot_sync(0xFFFFFFFFu, act);
    if (m == 0) return;
    int leader = __ffs(m) - 1;
    int base = 0;
    if (lane == leader) base = atomicAdd(&g_scratch[2 * M + g], __popc(m));
    base = __shfl_sync(0xFFFFFFFFu, base, leader);
    if (act) {
        int rank = __popc(m & ((1u << lane) - 1));
        g_wl[g][base + rank] = n;
    }
}

// Weighted packed accumulate of one uint4 (8 halves) with weight w.
__device__ __forceinline__ void facc4(u64* acc, uint4 p, u64 ww) {
    acc[0] = fma2v(h2f2(p.x), ww, acc[0]);
    acc[1] = fma2v(h2f2(p.y), ww, acc[1]);
    acc[2] = fma2v(h2f2(p.z), ww, acc[2]);
    acc[3] = fma2v(h2f2(p.w), ww, acc[3]);
}
// Unweighted packed accumulate.
__device__ __forceinline__ void aacc4(u64* acc, uint4 p) {
    acc[0] = add2v(h2f2(p.x), acc[0]);
    acc[1] = add2v(h2f2(p.y), acc[1]);
    acc[2] = add2v(h2f2(p.z), acc[2]);
    acc[3] = add2v(h2f2(p.w), acc[3]);
}

__device__ __forceinline__ void store_acc(__half* dst, const u64* acc, float sc, int lane) {
    u64 scp = packf2(sc, sc);
    __half2 o[4];
    #pragma unroll
    for (int i = 0; i < 4; i++) {
        float2 f = unpackf2(mul2v(acc[i], scp));
        o[i] = __floats2half2_rn(f.x, f.y);
    }
    reinterpret_cast<uint4*>(dst)[lane] = *reinterpret_cast<uint4*>(o);
}

// Layer 1: h~1[n] = dinv[n]^2 * sum_s dinv[s]*h0[s], 8 lanes/node, x4 unroll, f32x2 math.
__global__ void layer1_kernel(int N) {
    int g = blockIdx.y;
    int t = blockIdx.x * blockDim.x + threadIdx.x;
    int n = t >> 3, lane = t & 7;
    if (n >= N) return;
    int gn = g * N + n;
    const float* dinv = g_dinv + g * N;
    const uint4* hi = reinterpret_cast<const uint4*>(g_h0);
    const int* csr = g_csr + (size_t)gn * PAD;
    int deg = g_scratch[gn]; if (deg > PAD) deg = PAD;
    u64 acc[4] = {0ull, 0ull, 0ull, 0ull};
    int e = 0;
    for (; e + 4 <= deg; e += 4) {
        int s0 = csr[e], s1 = csr[e + 1], s2 = csr[e + 2], s3 = csr[e + 3];
        float w0 = dinv[s0], w1 = dinv[s1], w2 = dinv[s2], w3 = dinv[s3];
        uint4 p0 = hi[(size_t)s0 * 8 + lane];
        uint4 p1 = hi[(size_t)s1 * 8 + lane];
        uint4 p2 = hi[(size_t)s2 * 8 + lane];
        uint4 p3 = hi[(size_t)s3 * 8 + lane];
        facc4(acc, p0, packf2(w0, w0));
        facc4(acc, p1, packf2(w1, w1));
        facc4(acc, p2, packf2(w2, w2));
        facc4(acc, p3, packf2(w3, w3));
    }
    for (; e < deg; e++) {
        int s = csr[e];
        float w = dinv[s];
        facc4(acc, hi[(size_t)s * 8 + lane], packf2(w, w));
    }
    float dn = dinv[n];
    store_acc(&g_hb0[g][(size_t)n * DD], acc, dn * dn, lane);
}

// Layer 2 (compacted): only worklist nodes. h~2[n] = dinv[n]^2 * sum_s h~1[s].
__global__ void layer2_kernel(int N, int M) {
    int g = blockIdx.y;
    int t = blockIdx.x * blockDim.x + threadIdx.x;
    int j = t >> 3, lane = t & 7;
    if (j >= g_scratch[2 * M + g]) return;
    int n = g_wl[g][j];
    int gn = g * N + n;
    const uint4* hi = reinterpret_cast<const uint4*>(g_hb0[g]);
    const int* csr = g_csr + (size_t)gn * PAD;
    int deg = g_scratch[gn]; if (deg > PAD) deg = PAD;
    u64 acc[4] = {0ull, 0ull, 0ull, 0ull};
    int e = 0;
    for (; e + 4 <= deg; e += 4) {
        int s0 = csr[e], s1 = csr[e + 1], s2 = csr[e + 2], s3 = csr[e + 3];
        uint4 p0 = hi[(size_t)s0 * 8 + lane];
        uint4 p1 = hi[(size_t)s1 * 8 + lane];
        uint4 p2 = hi[(size_t)s2 * 8 + lane];
        uint4 p3 = hi[(size_t)s3 * 8 + lane];
        aacc4(acc, p0);
        aacc4(acc, p1);
        aacc4(acc, p2);
        aacc4(acc, p3);
    }
    for (; e < deg; e++) aacc4(acc, hi[(size_t)csr[e] * 8 + lane]);
    float dn = g_dinv[gn];
    store_acc(&g_hb1[g][(size_t)n * DD], acc, dn * dn, lane);
}

__global__ void wa_kernel(const float* __restrict__ W, const float* __restrict__ a) {
    int k = threadIdx.x;
    float s = 0.f;
    #pragma unroll
    for (int j = 0; j < DD; j++) s += W[k * DD + j] * a[j];
    g_wa[k] = s;
}

__device__ __forceinline__ float warp_sum(float p) {
    #pragma unroll
    for (int o = 16; o > 0; o >>= 1) p += __shfl_xor_sync(0xFFFFFFFFu, p, o);
    return p;
}

// 32-lane pull of one hb1 row: lane holds elements {2*lane, 2*lane+1}. Packed adds.
__device__ __forceinline__ float2 pull_row32u(const unsigned int* hi, const int* csr,
                                              int deg, int lane) {
    u64 acc = 0ull;
    int e = 0;
    for (; e + 4 <= deg; e += 4) {
        int s0 = csr[e], s1 = csr[e + 1], s2 = csr[e + 2], s3 = csr[e + 3];
        u64 f0 = h2f2(hi[(size_t)s0 * 32 + lane]);
        u64 f1 = h2f2(hi[(size_t)s1 * 32 + lane]);
        u64 f2 = h2f2(hi[(size_t)s2 * 32 + lane]);
        u64 f3 = h2f2(hi[(size_t)s3 * 32 + lane]);
        acc = add2v(acc, add2v(add2v(f0, f1), add2v(f2, f3)));
    }
    for (; e < deg; e++) acc = add2v(acc, h2f2(hi[(size_t)csr[e] * 32 + lane]));
    return unpackf2(acc);
}

// Fused layer-3 + epilogue: one warp per pair. Lane l holds elements {2l, 2l+1}.
__global__ void final_kernel(const int* __restrict__ user, const int* __restrict__ item,
                             float* __restrict__ out, int B, int N) {
    int w = (blockIdx.x * blockDim.x + threadIdx.x) >> 5;
    int lane = threadIdx.x & 31;
    if (w >= B) return;
    int u = user[w], it = item[w];

    float wa0 = g_wa[2 * lane], wa1 = g_wa[2 * lane + 1];

    float eu[3][2], ev[3][2], su[3], sv[3];
    #pragma unroll
    for (int g = 0; g < 3; g++) {
        const unsigned int* hi = reinterpret_cast<const unsigned int*>(g_hb1[g]);
        int gu = g * N + u, gi = g * N + it;
        int du = g_scratch[gu]; if (du > PAD) du = PAD;
        int di = g_scratch[gi]; if (di > PAD) di = PAD;
        float2 au = pull_row32u(hi, g_csr + (size_t)gu * PAD, du, lane);
        float2 ai = pull_row32u(hi, g_csr + (size_t)gi * PAD, di, lane);
        float dnu = g_dinv[gu], dni = g_dinv[gi];
        eu[g][0] = au.x * dnu; eu[g][1] = au.y * dnu;
        ev[g][0] = ai.x * dni; ev[g][1] = ai.y * dni;
        su[g] = warp_sum(eu[g][0] * wa0 + eu[g][1] * wa1);
        sv[g] = warp_sum(ev[g][0] * wa0 + ev[g][1] * wa1);
    }

    float mu = fmaxf(su[0], fmaxf(su[1], su[2]));
    float a0 = __expf(su[0] - mu), a1 = __expf(su[1] - mu), a2 = __expf(su[2] - mu);
    float ainv = 1.0f / (a0 + a1 + a2);
    float wu0 = a0 * ainv, wu1 = a1 * ainv, wu2 = a2 * ainv;
    float mv = fmaxf(sv[0], fmaxf(sv[1], sv[2]));
    float b0 = __expf(sv[0] - mv), b1 = __expf(sv[1] - mv), b2 = __expf(sv[2] - mv);
    float binv = 1.0f / (b0 + b1 + b2);
    float wv0 = b0 * binv, wv1 = b1 * binv, wv2 = b2 * binv;

    float nu0 = wu0 * eu[0][0] + wu1 * eu[1][0] + wu2 * eu[2][0];
    float nu1 = wu0 * eu[0][1] + wu1 * eu[1][1] + wu2 * eu[2][1];
    float ni0 = wv0 * ev[0][0] + wv1 * ev[1][0] + wv2 * ev[2][0];
    float ni1 = wv0 * ev[0][1] + wv1 * ev[1][1] + wv2 * ev[2][1];

    float dot = warp_sum(nu0 * ni0 + nu1 * ni1);
    if (lane == 0) out[w] = dot;
}

extern "C" void kernel_launch(void* const* d_in, const int* in_sizes, int n_in,
                              void* d_out, int out_size) {
    const int*   user = (const int*)d_in[0];
    const int*   item = (const int*)d_in[1];
    const int*   x    = (const int*)d_in[2];
    const int*   e0   = (const int*)d_in[3];
    const int*   e1   = (const int*)d_in[4];
    const int*   e2   = (const int*)d_in[5];
    const float* emb  = (const float*)d_in[6];
    const float* W    = (const float*)d_in[7];
    const float* a    = (const float*)d_in[8];
    float* out = (float*)d_out;

    int B = in_sizes[0];
    int N = in_sizes[2];
    int E = in_sizes[3] / 2;
    if (N > NMAX || E > EMAX || B > BMAX) return;

    const int T = 256;
    int M = 3 * N;
    int nb_E4 = ((E + 3) / 4 + T - 1) / T;
    int nb_M4 = ((M + 3) / 4 + T - 1) / T;
    int nb_N  = (N + T - 1) / T;
    int nb_N8 = (int)(((long long)N * 8 + T - 1) / T);
    int nb_P  = (2 * B + T - 1) / T;

    dim3 gridE(nb_E4, 3), gridL(nb_N8, 3), gridC(nb_N, 3);

    // Clear deg + flags + counts, and the pair bitmap (graph-capturable memsets).
    void* scratch_ptr = nullptr;
    cudaGetSymbolAddress(&scratch_ptr, g_scratch);
    cudaMemsetAsync(scratch_ptr, 0, ((size_t)2 * M + 8) * sizeof(int));
    void* bm_ptr = nullptr;
    cudaGetSymbolAddress(&bm_ptr, g_pairbm);
    cudaMemsetAsync(bm_ptr, 0, sizeof(unsigned int) * ((NMAX + 31) / 32));

    pairbm_kernel<<<nb_P, T>>>(user, item, B);
    build_h0_kernel<<<nb_N8, T>>>(emb, x, N);
    fill_csr_kernel<<<gridE, T>>>(e0, e1, e2, E, N, M);   // count + place + flag
    dinv_kernel<<<nb_M4, T>>>(M);
    compact_kernel<<<gridC, T>>>(N, M);

    layer1_kernel<<<gridL, T>>>(N);
    layer2_kernel<<<gridL, T>>>(N, M);

    wa_kernel<<<1, DD>>>(W, a);
    final_kernel<<<(B * 32 + T - 1) / T, T>>>(user, item, out, B, N);
}